// round 2
// baseline (speedup 1.0000x reference)
#include <cuda_runtime.h>
#include <cfloat>

#define BATCH 8
#define TPTS 30000
#define NPTS (BATCH*TPTS)          // 240000
#define H 128
#define H2 256
#define R2 4096
#define PTILE 128
#define NTILES (NPTS/PTILE)        // 1875
#define PSTRIDE 132                // multiple of 4 -> 16B-aligned rows
#define CNTN (3*BATCH*R2)          // 98304

typedef unsigned long long u64;

// ---- device scratch ----
__device__ float g_net[(size_t)NPTS * H];      // ~123 MB
__device__ float g_c[(size_t)NPTS * H];        // ~123 MB
__device__ float g_plane[(size_t)CNTN * H];    // ~50 MB
__device__ int   g_cnt[CNTN];
__device__ int   g_start[CNTN];
__device__ int   g_cursor[CNTN];
__device__ int   g_sorted[3 * NPTS];
__device__ int   g_bsum[96];

// ---- packed f32x2 helpers ----
__device__ __forceinline__ u64 pack2(float x) {
    u64 r; asm("mov.b64 %0, {%1, %1};" : "=l"(r) : "f"(x)); return r;
}
__device__ __forceinline__ u64 pack2v(float lo, float hi) {
    u64 r; asm("mov.b64 %0, {%1, %2};" : "=l"(r) : "f"(lo), "f"(hi)); return r;
}
__device__ __forceinline__ void ffma2(u64 &d, u64 a, u64 b) {
    asm("fma.rn.f32x2 %0, %1, %2, %0;" : "+l"(d) : "l"(a), "l"(b));
}
__device__ __forceinline__ void unpack2(u64 v, float &lo, float &hi) {
    asm("mov.b64 {%0, %1}, %2;" : "=f"(lo), "=f"(hi) : "l"(v));
}

// ---- duplicated-B weight chunk loader: 8 rows x 128 cols -> u64[8][128] (each w dup'd) ----
__device__ __forceinline__ void load_wdup(u64* dst, const float* __restrict__ W,
                                          int chunk, int tid) {
    int idx = tid * 2;               // 512 threads * 2 = 1024 floats
    int r = idx >> 7;
    int c = idx & 127;
    float2 v = *(const float2*)(W + (size_t)(chunk * 8 + r) * H + c);
    ulonglong2 d;
    d.x = pack2(v.x);
    d.y = pack2(v.y);
    *(ulonglong2*)(dst + r * 128 + c) = d;   // 16B aligned (c even)
}

// ---- GEMM stage: acc[pair][col8] += (relu?)A[k][p-pair] * Wdup[k][col] ----
// 512 threads: tx = tid&15 (cols tx*4..+3 and 64+tx*4..+3), ty = tid>>4 (points ty*4..+3)
template<bool RELUA>
__device__ __forceinline__ void gemm_stage(const float* A, int kdim,
                                           const float* __restrict__ W,
                                           u64* wbd, u64 acc[2][8],
                                           int ty, int tx, int tid) {
    int nch = kdim >> 3;
    load_wdup(wbd, W, 0, tid);
    __syncthreads();
    for (int ch = 0; ch < nch; ch++) {
        u64* cur = wbd + (ch & 1) * 1024;
        if (ch + 1 < nch) load_wdup(wbd + ((ch + 1) & 1) * 1024, W, ch + 1, tid);
#pragma unroll
        for (int kk = 0; kk < 8; kk++) {
            const float* arow = A + (size_t)(ch * 8 + kk) * PSTRIDE + ty * 4;
            float4 av = *(const float4*)arow;           // 4 points, 2 packed pairs
            if (RELUA) {
                av.x = fmaxf(av.x, 0.f); av.y = fmaxf(av.y, 0.f);
                av.z = fmaxf(av.z, 0.f); av.w = fmaxf(av.w, 0.f);
            }
            u64 a0 = pack2v(av.x, av.y);
            u64 a1 = pack2v(av.z, av.w);
            const u64* br = cur + (size_t)kk * 128;
            ulonglong2 q0 = *(const ulonglong2*)(br + tx * 4);
            ulonglong2 q1 = *(const ulonglong2*)(br + tx * 4 + 2);
            ulonglong2 q2 = *(const ulonglong2*)(br + 64 + tx * 4);
            ulonglong2 q3 = *(const ulonglong2*)(br + 64 + tx * 4 + 2);
            ffma2(acc[0][0], a0, q0.x); ffma2(acc[1][0], a1, q0.x);
            ffma2(acc[0][1], a0, q0.y); ffma2(acc[1][1], a1, q0.y);
            ffma2(acc[0][2], a0, q1.x); ffma2(acc[1][2], a1, q1.x);
            ffma2(acc[0][3], a0, q1.y); ffma2(acc[1][3], a1, q1.y);
            ffma2(acc[0][4], a0, q2.x); ffma2(acc[1][4], a1, q2.x);
            ffma2(acc[0][5], a0, q2.y); ffma2(acc[1][5], a1, q2.y);
            ffma2(acc[0][6], a0, q3.x); ffma2(acc[1][6], a1, q3.x);
            ffma2(acc[0][7], a0, q3.y); ffma2(acc[1][7], a1, q3.y);
        }
        __syncthreads();
    }
}

// ---- fused resnet block ----
__global__ void __launch_bounds__(512, 1)
resnet_kernel(int mode,
              const float* __restrict__ pts,
              const int* __restrict__ ixz, const int* __restrict__ ixy,
              const int* __restrict__ iyz,
              const float* __restrict__ fcpw, const float* __restrict__ fcpb,
              const float* __restrict__ w0, const float* __restrict__ b0,
              const float* __restrict__ w1, const float* __restrict__ b1,
              const float* __restrict__ wsc) {
    extern __shared__ float sm[];
    float* xs = sm;                           // [H2][PSTRIDE] raw input
    float* ns = xs + H2 * PSTRIDE;            // [H][PSTRIDE] relu(net1)
    u64*   wbd = (u64*)(ns + H * PSTRIDE);    // 2 x [8][128] dup'd weights

    int tid = threadIdx.x;
    int pbase = blockIdx.x * PTILE;

    // ---- fill xs raw ----
    {
        int k = tid & 255;
        int s0 = (tid >> 8) * 64;
        if (mode == 0) {
            float wk0 = fcpw[k], wk1 = fcpw[256 + k], wk2 = fcpw[512 + k];
            float bk = fcpb[k];
            for (int s = s0; s < s0 + 64; s++) {
                int gp = pbase + s;
                float p0 = pts[gp * 3 + 0], p1 = pts[gp * 3 + 1], p2 = pts[gp * 3 + 2];
                xs[k * PSTRIDE + s] = bk + p0 * wk0 + p1 * wk1 + p2 * wk2;
            }
        } else if (k < H) {
            for (int s = s0; s < s0 + 64; s++) {
                int gp = pbase + s;
                xs[k * PSTRIDE + s] = g_net[(size_t)gp * H + k];
            }
        } else {
            int ch = k - H;
            for (int s = s0; s < s0 + 64; s++) {
                int gp = pbase + s;
                int b = gp / TPTS;
                int i0 = ixz[gp], i1 = ixy[gp], i2 = iyz[gp];
                float v = g_plane[((size_t)(0 * BATCH + b) * R2 + i0) * H + ch]
                        + g_plane[((size_t)(1 * BATCH + b) * R2 + i1) * H + ch]
                        + g_plane[((size_t)(2 * BATCH + b) * R2 + i2) * H + ch];
                xs[k * PSTRIDE + s] = v;
            }
        }
    }
    __syncthreads();

    int tx = tid & 15, ty = tid >> 4;
    int c0 = tx * 4, c1 = 64 + tx * 4;

    u64 acc[2][8];
#pragma unroll
    for (int i = 0; i < 2; i++)
#pragma unroll
        for (int j = 0; j < 8; j++) acc[i][j] = 0ULL;

    // stage 0: net1 = relu(x) @ w0 + b0; ns = relu(net1)
    gemm_stage<true>(xs, H2, w0, wbd, acc, ty, tx, tid);
    {
        float bb[8];
#pragma unroll
        for (int j = 0; j < 4; j++) { bb[j] = b0[c0 + j]; bb[4 + j] = b0[c1 + j]; }
#pragma unroll
        for (int j = 0; j < 8; j++) {
            int c = (j < 4) ? (c0 + j) : (c1 + j - 4);
            float l0, h0, l1, h1;
            unpack2(acc[0][j], l0, h0);
            unpack2(acc[1][j], l1, h1);
            float4 o = make_float4(fmaxf(l0 + bb[j], 0.f), fmaxf(h0 + bb[j], 0.f),
                                   fmaxf(l1 + bb[j], 0.f), fmaxf(h1 + bb[j], 0.f));
            *(float4*)(ns + (size_t)c * PSTRIDE + ty * 4) = o;
        }
    }
    __syncthreads();

    // stages sc + 1: out = x @ wsc + relu(net1) @ w1 + b1
#pragma unroll
    for (int i = 0; i < 2; i++)
#pragma unroll
        for (int j = 0; j < 8; j++) acc[i][j] = 0ULL;

    gemm_stage<false>(xs, H2, wsc, wbd, acc, ty, tx, tid);
    gemm_stage<false>(ns, H,  w1,  wbd, acc, ty, tx, tid);

    {
        float bb[8];
#pragma unroll
        for (int j = 0; j < 4; j++) { bb[j] = b1[c0 + j]; bb[4 + j] = b1[c1 + j]; }
        float vl[2][8], vh[2][8];
#pragma unroll
        for (int i = 0; i < 2; i++)
#pragma unroll
            for (int j = 0; j < 8; j++) unpack2(acc[i][j], vl[i][j], vh[i][j]);
#pragma unroll
        for (int i = 0; i < 2; i++) {
#pragma unroll
            for (int h = 0; h < 2; h++) {
                int gp = pbase + ty * 4 + i * 2 + h;
                float* row = h ? vh[i] : vl[i];
                float4 o0 = make_float4(row[0] + bb[0], row[1] + bb[1],
                                        row[2] + bb[2], row[3] + bb[3]);
                float4 o1 = make_float4(row[4] + bb[4], row[5] + bb[5],
                                        row[6] + bb[6], row[7] + bb[7]);
                *(float4*)(&g_net[(size_t)gp * H + c0]) = o0;
                *(float4*)(&g_net[(size_t)gp * H + c1]) = o1;
            }
        }
    }
}

// ---- final projection: c = net @ wc + bc -> g_c ----
__global__ void __launch_bounds__(512, 1)
proj_kernel(const float* __restrict__ wc, const float* __restrict__ bc) {
    extern __shared__ float sm[];
    float* xs = sm;                         // [H][PSTRIDE]
    u64*   wbd = (u64*)(xs + H * PSTRIDE);

    int tid = threadIdx.x;
    int pbase = blockIdx.x * PTILE;
    {
        int k = tid & 127;
        int s0 = (tid >> 7) * 32;
        for (int s = s0; s < s0 + 32; s++) {
            int gp = pbase + s;
            xs[k * PSTRIDE + s] = g_net[(size_t)gp * H + k];
        }
    }
    __syncthreads();

    int tx = tid & 15, ty = tid >> 4;
    int c0 = tx * 4, c1 = 64 + tx * 4;

    u64 acc[2][8];
#pragma unroll
    for (int i = 0; i < 2; i++)
#pragma unroll
        for (int j = 0; j < 8; j++) acc[i][j] = 0ULL;

    gemm_stage<false>(xs, H, wc, wbd, acc, ty, tx, tid);

    float bb[8];
#pragma unroll
    for (int j = 0; j < 4; j++) { bb[j] = bc[c0 + j]; bb[4 + j] = bc[c1 + j]; }
    float vl[2][8], vh[2][8];
#pragma unroll
    for (int i = 0; i < 2; i++)
#pragma unroll
        for (int j = 0; j < 8; j++) unpack2(acc[i][j], vl[i][j], vh[i][j]);
#pragma unroll
    for (int i = 0; i < 2; i++) {
#pragma unroll
        for (int h = 0; h < 2; h++) {
            int gp = pbase + ty * 4 + i * 2 + h;
            float* row = h ? vh[i] : vl[i];
            float4 o0 = make_float4(row[0] + bb[0], row[1] + bb[1],
                                    row[2] + bb[2], row[3] + bb[3]);
            float4 o1 = make_float4(row[4] + bb[4], row[5] + bb[5],
                                    row[6] + bb[6], row[7] + bb[7]);
            *(float4*)(&g_c[(size_t)gp * H + c0]) = o0;
            *(float4*)(&g_c[(size_t)gp * H + c1]) = o1;
        }
    }
}

// ============ sorted-bin infrastructure (runs once per call) ============

__global__ void zero_meta_kernel() {
    int i = blockIdx.x * 256 + threadIdx.x;
    if (i < CNTN) { g_cnt[i] = 0; g_cursor[i] = 0; }
}

__global__ void count_kernel(const int* __restrict__ ixz,
                             const int* __restrict__ ixy,
                             const int* __restrict__ iyz) {
    int p = blockIdx.x * 256 + threadIdx.x;
    if (p >= NPTS) return;
    int b = p / TPTS;
    atomicAdd(&g_cnt[(0 * BATCH + b) * R2 + ixz[p]], 1);
    atomicAdd(&g_cnt[(1 * BATCH + b) * R2 + ixy[p]], 1);
    atomicAdd(&g_cnt[(2 * BATCH + b) * R2 + iyz[p]], 1);
}

__global__ void scan1_kernel() {         // 96 blocks x 1024 threads
    __shared__ int smv[1024];
    int tid = threadIdx.x;
    int i = blockIdx.x * 1024 + tid;
    int v = g_cnt[i];
    smv[tid] = v;
    __syncthreads();
    for (int off = 1; off < 1024; off <<= 1) {
        int t = 0;
        if (tid >= off) t = smv[tid - off];
        __syncthreads();
        if (tid >= off) smv[tid] += t;
        __syncthreads();
    }
    g_start[i] = smv[tid] - v;           // exclusive (within block)
    if (tid == 1023) g_bsum[blockIdx.x] = smv[tid];
}

__global__ void scan2_kernel() {         // 1 block x 128 threads over 96 sums
    __shared__ int smv[128];
    int tid = threadIdx.x;
    int v = (tid < 96) ? g_bsum[tid] : 0;
    smv[tid] = v;
    __syncthreads();
    for (int off = 1; off < 128; off <<= 1) {
        int t = 0;
        if (tid >= off) t = smv[tid - off];
        __syncthreads();
        if (tid >= off) smv[tid] += t;
        __syncthreads();
    }
    if (tid < 96) g_bsum[tid] = smv[tid] - v;   // exclusive
}

__global__ void scan3_kernel() {
    int i = blockIdx.x * 256 + threadIdx.x;
    if (i < CNTN) g_start[i] += g_bsum[i >> 10];
}

__global__ void sortfill_kernel(const int* __restrict__ ixz,
                                const int* __restrict__ ixy,
                                const int* __restrict__ iyz) {
    int p = blockIdx.x * 256 + threadIdx.x;
    if (p >= NPTS) return;
    int b = p / TPTS;
    int bins[3];
    bins[0] = (0 * BATCH + b) * R2 + ixz[p];
    bins[1] = (1 * BATCH + b) * R2 + ixy[p];
    bins[2] = (2 * BATCH + b) * R2 + iyz[p];
#pragma unroll
    for (int pl = 0; pl < 3; pl++) {
        int bin = bins[pl];
        int pos = atomicAdd(&g_cursor[bin], 1);
        g_sorted[g_start[bin] + pos] = p;
    }
}

// ---- pool max: per-bin gather-max over sorted point lists ----
__global__ void pool_max_kernel() {      // grid = CNTN, block = 128
    int bin = blockIdx.x;
    int n = g_cnt[bin];
    if (n == 0) return;
    int st = g_start[bin];
    int ch = threadIdx.x;
    float v = -FLT_MAX;
    int i = 0;
    for (; i + 4 <= n; i += 4) {
        int p0 = g_sorted[st + i + 0];
        int p1 = g_sorted[st + i + 1];
        int p2 = g_sorted[st + i + 2];
        int p3 = g_sorted[st + i + 3];
        float a = g_net[(size_t)p0 * H + ch];
        float b = g_net[(size_t)p1 * H + ch];
        float c = g_net[(size_t)p2 * H + ch];
        float d = g_net[(size_t)p3 * H + ch];
        v = fmaxf(v, fmaxf(fmaxf(a, b), fmaxf(c, d)));
    }
    for (; i < n; i++) {
        int p = g_sorted[st + i];
        v = fmaxf(v, g_net[(size_t)p * H + ch]);
    }
    g_plane[(size_t)bin * H + ch] = v;
}

// ---- plane mean: per-bin gather-sum, smem-transposed coalesced writes ----
__global__ void __launch_bounds__(128)
mean_kernel(float* __restrict__ out) {   // grid = 24*128 = 3072, block = 128
    __shared__ float tile[128][33];
    int pb = blockIdx.x >> 7;            // plane*BATCH + batch (0..23)
    int r0 = (blockIdx.x & 127) * 32;
    int ch = threadIdx.x;

    for (int bb = 0; bb < 32; bb++) {
        int bin = pb * R2 + r0 + bb;
        int n = g_cnt[bin];
        int st = g_start[bin];
        float s = 0.f;
        int i = 0;
        for (; i + 4 <= n; i += 4) {
            int p0 = g_sorted[st + i + 0];
            int p1 = g_sorted[st + i + 1];
            int p2 = g_sorted[st + i + 2];
            int p3 = g_sorted[st + i + 3];
            s += g_c[(size_t)p0 * H + ch] + g_c[(size_t)p1 * H + ch]
               + g_c[(size_t)p2 * H + ch] + g_c[(size_t)p3 * H + ch];
        }
        for (; i < n; i++) s += g_c[(size_t)g_sorted[st + i] * H + ch];
        tile[ch][bb] = s / (float)max(n, 1);
    }
    __syncthreads();

    int lane = ch & 31;
    int rowq = ch >> 5;
    for (int it = 0; it < 32; it++) {
        int row = it * 4 + rowq;
        out[((size_t)pb * H + row) * R2 + r0 + lane] = tile[row][lane];
    }
}

extern "C" void kernel_launch(void* const* d_in, const int* in_sizes, int n_in,
                              void* d_out, int out_size) {
    const float* pts  = (const float*)d_in[0];
    const int*   ixz  = (const int*)d_in[1];
    const int*   ixy  = (const int*)d_in[2];
    const int*   iyz  = (const int*)d_in[3];
    const float* fcpw = (const float*)d_in[4];
    const float* fcpb = (const float*)d_in[5];
    const float* fc0w = (const float*)d_in[6];
    const float* fc0b = (const float*)d_in[7];
    const float* fc1w = (const float*)d_in[8];
    const float* fc1b = (const float*)d_in[9];
    const float* scw  = (const float*)d_in[10];
    const float* fccw = (const float*)d_in[11];
    const float* fccb = (const float*)d_in[12];
    float* out = (float*)d_out;

    const int RSMEM = ((H2 + H) * PSTRIDE) * 4 + 2048 * 8;   // 219136
    const int FSMEM = (H * PSTRIDE) * 4 + 2048 * 8;          //  83968
    cudaFuncSetAttribute(resnet_kernel, cudaFuncAttributeMaxDynamicSharedMemorySize, RSMEM);
    cudaFuncSetAttribute(proj_kernel,   cudaFuncAttributeMaxDynamicSharedMemorySize, FSMEM);

    // sorted-bin infra (indices fixed for this call)
    zero_meta_kernel<<<(CNTN + 255) / 256, 256>>>();
    count_kernel<<<(NPTS + 255) / 256, 256>>>(ixz, ixy, iyz);
    scan1_kernel<<<96, 1024>>>();
    scan2_kernel<<<1, 128>>>();
    scan3_kernel<<<(CNTN + 255) / 256, 256>>>();
    sortfill_kernel<<<(NPTS + 255) / 256, 256>>>(ixz, ixy, iyz);

    // block 0 (fc_pos fused)
    resnet_kernel<<<NTILES, 512, RSMEM>>>(0, pts, ixz, ixy, iyz, fcpw, fcpb,
                                          fc0w, fc0b, fc1w, fc1b, scw);
    // blocks 1..4 with pooling
    for (int it = 1; it < 5; it++) {
        pool_max_kernel<<<CNTN, 128>>>();
        resnet_kernel<<<NTILES, 512, RSMEM>>>(1, pts, ixz, ixy, iyz, fcpw, fcpb,
                                              fc0w + (size_t)it * H2 * H,
                                              fc0b + (size_t)it * H,
                                              fc1w + (size_t)it * H * H,
                                              fc1b + (size_t)it * H,
                                              scw  + (size_t)it * H2 * H);
    }
    // final projection + plane means
    proj_kernel<<<NTILES, 512, FSMEM>>>(fccw, fccb);
    mean_kernel<<<24 * 128, 128>>>(out);
}

// round 3
// speedup vs baseline: 2.1464x; 2.1464x over previous
#include <cuda_runtime.h>
#include <cfloat>

#define BATCH 8
#define TPTS 30000
#define NPTS (BATCH*TPTS)          // 240000
#define H 128
#define H2 256
#define R2 4096
#define PTILE 128
#define NTILES (NPTS/PTILE)        // 1875
#define PSTRIDE 132                // 132 floats = 528B = 33*16 -> 16B-aligned rows
#define CNTN (3*BATCH*R2)          // 98304
#define KC 16

typedef unsigned long long u64;

// ---- device scratch ----
__device__ float g_net[(size_t)NPTS * H];
__device__ float g_c[(size_t)NPTS * H];
__device__ float g_plane[(size_t)CNTN * H];
__device__ int   g_cnt[CNTN];
__device__ int   g_start[CNTN];
__device__ int   g_cursor[CNTN];
__device__ int   g_sorted[3 * NPTS];
__device__ int   g_bsum[96];

// ---- packed f32x2 helpers ----
__device__ __forceinline__ u64 pack2(float x) {
    u64 r; asm("mov.b64 %0, {%1, %1};" : "=l"(r) : "f"(x)); return r;
}
__device__ __forceinline__ void ffma2(u64 &d, u64 a, u64 b) {
    asm("fma.rn.f32x2 %0, %1, %2, %0;" : "+l"(d) : "l"(a), "l"(b));
}
__device__ __forceinline__ void unpack2(u64 v, float &lo, float &hi) {
    asm("mov.b64 {%0, %1}, %2;" : "=f"(lo), "=f"(hi) : "l"(v));
}

// ---- weight chunk loader: KC rows x 128 cols, one float4 per thread (512 thr) ----
__device__ __forceinline__ void load_w(float* dst, const float* __restrict__ W,
                                       int chunk, int tid) {
    int r = tid >> 5;              // 0..15
    int c = (tid & 31) << 2;       // 0..124
    float4 v = *(const float4*)(W + (size_t)(chunk * KC + r) * H + c);
    *(float4*)(dst + r * 128 + c) = v;
}

// ---- GEMM stage ----
// CTA tile 128 pts x 128 cols, 512 threads, warp grid 4(pt) x 4(col),
// lane grid 8(pt) x 4(col). Thread: 4 pts x 8 cols (4 f32x2 col-pairs).
// acc[p][j]: point p, cols (c0+2j, c0+2j+1).
template<bool RELUA>
__device__ __forceinline__ void gemm_stage(const float* A, int kdim,
                                           const float* __restrict__ W,
                                           float* wb, u64 acc[4][4],
                                           int pt0, int c0, int tid) {
    int nch = kdim >> 4;
    load_w(wb, W, 0, tid);
    __syncthreads();
    int qidx = c0 >> 2;                       // ulonglong2 index of first 4 cols
    for (int ch = 0; ch < nch; ch++) {
        const float* cur = wb + (ch & 1) * (KC * 128);
        if (ch + 1 < nch) load_w(wb + ((ch + 1) & 1) * (KC * 128), W, ch + 1, tid);
#pragma unroll
        for (int kk = 0; kk < KC; kk++) {
            float4 av = *(const float4*)(A + (size_t)(ch * KC + kk) * PSTRIDE + pt0);
            if (RELUA) {
                av.x = fmaxf(av.x, 0.f); av.y = fmaxf(av.y, 0.f);
                av.z = fmaxf(av.z, 0.f); av.w = fmaxf(av.w, 0.f);
            }
            u64 a0 = pack2(av.x), a1 = pack2(av.y), a2 = pack2(av.z), a3 = pack2(av.w);
            const ulonglong2* brow = (const ulonglong2*)(cur + kk * 128);
            ulonglong2 q0 = brow[qidx];       // cols c0..c0+3 (2 pairs)
            ulonglong2 q1 = brow[qidx + 1];   // cols c0+4..c0+7
            ffma2(acc[0][0], a0, q0.x); ffma2(acc[0][1], a0, q0.y);
            ffma2(acc[0][2], a0, q1.x); ffma2(acc[0][3], a0, q1.y);
            ffma2(acc[1][0], a1, q0.x); ffma2(acc[1][1], a1, q0.y);
            ffma2(acc[1][2], a1, q1.x); ffma2(acc[1][3], a1, q1.y);
            ffma2(acc[2][0], a2, q0.x); ffma2(acc[2][1], a2, q0.y);
            ffma2(acc[2][2], a2, q1.x); ffma2(acc[2][3], a2, q1.y);
            ffma2(acc[3][0], a3, q0.x); ffma2(acc[3][1], a3, q0.y);
            ffma2(acc[3][2], a3, q1.x); ffma2(acc[3][3], a3, q1.y);
        }
        __syncthreads();
    }
}

__device__ __forceinline__ void zero_acc(u64 acc[4][4]) {
#pragma unroll
    for (int i = 0; i < 4; i++)
#pragma unroll
        for (int j = 0; j < 4; j++) acc[i][j] = 0ULL;
}

// ---- fused resnet block ----
__global__ void __launch_bounds__(512, 1)
resnet_kernel(int mode,
              const float* __restrict__ pts,
              const int* __restrict__ ixz, const int* __restrict__ ixy,
              const int* __restrict__ iyz,
              const float* __restrict__ fcpw, const float* __restrict__ fcpb,
              const float* __restrict__ w0, const float* __restrict__ b0,
              const float* __restrict__ w1, const float* __restrict__ b1,
              const float* __restrict__ wsc) {
    extern __shared__ float sm[];
    float* xs = sm;                           // [H2][PSTRIDE] input x
    float* ns = xs + H2 * PSTRIDE;            // [H][PSTRIDE]  relu(net1)
    float* wb = ns + H * PSTRIDE;             // [2][KC][128]  weights
    int*   sbin = (int*)(wb + 2 * KC * 128);  // [3][PTILE]    pooled bin ids

    int tid = threadIdx.x;
    int pbase = blockIdx.x * PTILE;

    if (mode == 1) {
        if (tid < PTILE) {
            int gp = pbase + tid;
            int b = gp / TPTS;
            sbin[tid]             = (0 * BATCH + b) * R2 + ixz[gp];
            sbin[PTILE + tid]     = (1 * BATCH + b) * R2 + ixy[gp];
            sbin[2 * PTILE + tid] = (2 * BATCH + b) * R2 + iyz[gp];
        }
        __syncthreads();
    }

    // ---- fill xs[k][s] ----
    {
        int k = tid & 255;
        int s0 = (tid >> 8) * 64;
        if (mode == 0) {
            float wk0 = fcpw[k], wk1 = fcpw[256 + k], wk2 = fcpw[512 + k];
            float bk = fcpb[k];
            for (int s = s0; s < s0 + 64; s++) {
                int gp = pbase + s;
                float p0 = pts[gp * 3 + 0], p1 = pts[gp * 3 + 1], p2 = pts[gp * 3 + 2];
                xs[k * PSTRIDE + s] = bk + p0 * wk0 + p1 * wk1 + p2 * wk2;
            }
        } else if (k < H) {
            for (int s = s0; s < s0 + 64; s++) {
                int gp = pbase + s;
                xs[k * PSTRIDE + s] = g_net[(size_t)gp * H + k];
            }
        } else {
            int ch = k - H;
#pragma unroll 2
            for (int s = s0; s < s0 + 64; s++) {
                int b0i = sbin[s], b1i = sbin[PTILE + s], b2i = sbin[2 * PTILE + s];
                float v = g_plane[(size_t)b0i * H + ch]
                        + g_plane[(size_t)b1i * H + ch]
                        + g_plane[(size_t)b2i * H + ch];
                xs[k * PSTRIDE + s] = v;
            }
        }
    }
    __syncthreads();

    int cl = tid & 3;
    int pl = (tid >> 2) & 7;
    int wc = (tid >> 5) & 3;
    int wp = tid >> 7;
    int pt0 = wp * 32 + pl * 4;
    int c0 = wc * 32 + cl * 8;

    u64 acc[4][4];
    zero_acc(acc);

    // stage 0: ns = relu(relu(x) @ w0 + b0)
    gemm_stage<true>(xs, H2, w0, wb, acc, pt0, c0, tid);
    {
#pragma unroll
        for (int j = 0; j < 4; j++) {
            int clo = c0 + 2 * j, chi = clo + 1;
            float blo = b0[clo], bhi = b0[chi];
            float lo0, hi0, lo1, hi1, lo2, hi2, lo3, hi3;
            unpack2(acc[0][j], lo0, hi0);
            unpack2(acc[1][j], lo1, hi1);
            unpack2(acc[2][j], lo2, hi2);
            unpack2(acc[3][j], lo3, hi3);
            float4 vlo = make_float4(fmaxf(lo0 + blo, 0.f), fmaxf(lo1 + blo, 0.f),
                                     fmaxf(lo2 + blo, 0.f), fmaxf(lo3 + blo, 0.f));
            float4 vhi = make_float4(fmaxf(hi0 + bhi, 0.f), fmaxf(hi1 + bhi, 0.f),
                                     fmaxf(hi2 + bhi, 0.f), fmaxf(hi3 + bhi, 0.f));
            *(float4*)(ns + (size_t)clo * PSTRIDE + pt0) = vlo;
            *(float4*)(ns + (size_t)chi * PSTRIDE + pt0) = vhi;
        }
    }
    __syncthreads();

    // stage sc + stage 1: out = x @ wsc + ns @ w1 + b1
    zero_acc(acc);
    gemm_stage<false>(xs, H2, wsc, wb, acc, pt0, c0, tid);
    gemm_stage<false>(ns, H,  w1,  wb, acc, pt0, c0, tid);
    {
        float bb[8];
#pragma unroll
        for (int j = 0; j < 8; j++) bb[j] = b1[c0 + j];
#pragma unroll
        for (int p = 0; p < 4; p++) {
            int gp = pbase + pt0 + p;
            float f[8];
            unpack2(acc[p][0], f[0], f[1]);
            unpack2(acc[p][1], f[2], f[3]);
            unpack2(acc[p][2], f[4], f[5]);
            unpack2(acc[p][3], f[6], f[7]);
            float4 o0 = make_float4(f[0] + bb[0], f[1] + bb[1], f[2] + bb[2], f[3] + bb[3]);
            float4 o1 = make_float4(f[4] + bb[4], f[5] + bb[5], f[6] + bb[6], f[7] + bb[7]);
            *(float4*)(&g_net[(size_t)gp * H + c0]) = o0;
            *(float4*)(&g_net[(size_t)gp * H + c0 + 4]) = o1;
        }
    }
}

// ---- final projection: c = net @ wc + bc -> g_c ----
__global__ void __launch_bounds__(512, 1)
proj_kernel(const float* __restrict__ wc, const float* __restrict__ bc) {
    extern __shared__ float sm[];
    float* xs = sm;                         // [H][PSTRIDE]
    float* wb = xs + H * PSTRIDE;

    int tid = threadIdx.x;
    int pbase = blockIdx.x * PTILE;
    {
        int k = tid & 127;
        int s0 = (tid >> 7) * 32;
        for (int s = s0; s < s0 + 32; s++) {
            int gp = pbase + s;
            xs[k * PSTRIDE + s] = g_net[(size_t)gp * H + k];
        }
    }
    __syncthreads();

    int cl = tid & 3;
    int pl = (tid >> 2) & 7;
    int wc2 = (tid >> 5) & 3;
    int wp = tid >> 7;
    int pt0 = wp * 32 + pl * 4;
    int c0 = wc2 * 32 + cl * 8;

    u64 acc[4][4];
    zero_acc(acc);
    gemm_stage<false>(xs, H, wc, wb, acc, pt0, c0, tid);

    float bb[8];
#pragma unroll
    for (int j = 0; j < 8; j++) bb[j] = bc[c0 + j];
#pragma unroll
    for (int p = 0; p < 4; p++) {
        int gp = pbase + pt0 + p;
        float f[8];
        unpack2(acc[p][0], f[0], f[1]);
        unpack2(acc[p][1], f[2], f[3]);
        unpack2(acc[p][2], f[4], f[5]);
        unpack2(acc[p][3], f[6], f[7]);
        float4 o0 = make_float4(f[0] + bb[0], f[1] + bb[1], f[2] + bb[2], f[3] + bb[3]);
        float4 o1 = make_float4(f[4] + bb[4], f[5] + bb[5], f[6] + bb[6], f[7] + bb[7]);
        *(float4*)(&g_c[(size_t)gp * H + c0]) = o0;
        *(float4*)(&g_c[(size_t)gp * H + c0 + 4]) = o1;
    }
}

// ============ sorted-bin infrastructure (runs once per call) ============

__global__ void zero_meta_kernel() {
    int i = blockIdx.x * 256 + threadIdx.x;
    if (i < CNTN) { g_cnt[i] = 0; g_cursor[i] = 0; }
}

__global__ void count_kernel(const int* __restrict__ ixz,
                             const int* __restrict__ ixy,
                             const int* __restrict__ iyz) {
    int p = blockIdx.x * 256 + threadIdx.x;
    if (p >= NPTS) return;
    int b = p / TPTS;
    atomicAdd(&g_cnt[(0 * BATCH + b) * R2 + ixz[p]], 1);
    atomicAdd(&g_cnt[(1 * BATCH + b) * R2 + ixy[p]], 1);
    atomicAdd(&g_cnt[(2 * BATCH + b) * R2 + iyz[p]], 1);
}

__global__ void scan1_kernel() {         // 96 blocks x 1024 threads
    __shared__ int smv[1024];
    int tid = threadIdx.x;
    int i = blockIdx.x * 1024 + tid;
    int v = g_cnt[i];
    smv[tid] = v;
    __syncthreads();
    for (int off = 1; off < 1024; off <<= 1) {
        int t = 0;
        if (tid >= off) t = smv[tid - off];
        __syncthreads();
        if (tid >= off) smv[tid] += t;
        __syncthreads();
    }
    g_start[i] = smv[tid] - v;
    if (tid == 1023) g_bsum[blockIdx.x] = smv[tid];
}

__global__ void scan2_kernel() {         // 1 block x 128 threads over 96 sums
    __shared__ int smv[128];
    int tid = threadIdx.x;
    int v = (tid < 96) ? g_bsum[tid] : 0;
    smv[tid] = v;
    __syncthreads();
    for (int off = 1; off < 128; off <<= 1) {
        int t = 0;
        if (tid >= off) t = smv[tid - off];
        __syncthreads();
        if (tid >= off) smv[tid] += t;
        __syncthreads();
    }
    if (tid < 96) g_bsum[tid] = smv[tid] - v;
}

__global__ void scan3_kernel() {
    int i = blockIdx.x * 256 + threadIdx.x;
    if (i < CNTN) g_start[i] += g_bsum[i >> 10];
}

__global__ void sortfill_kernel(const int* __restrict__ ixz,
                                const int* __restrict__ ixy,
                                const int* __restrict__ iyz) {
    int p = blockIdx.x * 256 + threadIdx.x;
    if (p >= NPTS) return;
    int b = p / TPTS;
    int bins[3];
    bins[0] = (0 * BATCH + b) * R2 + ixz[p];
    bins[1] = (1 * BATCH + b) * R2 + ixy[p];
    bins[2] = (2 * BATCH + b) * R2 + iyz[p];
#pragma unroll
    for (int pl = 0; pl < 3; pl++) {
        int bin = bins[pl];
        int pos = atomicAdd(&g_cursor[bin], 1);
        g_sorted[g_start[bin] + pos] = p;
    }
}

// ---- pool max: per-bin gather-max over sorted point lists ----
__global__ void pool_max_kernel() {      // grid = CNTN, block = 128
    int bin = blockIdx.x;
    int n = g_cnt[bin];
    if (n == 0) return;
    int st = g_start[bin];
    int ch = threadIdx.x;
    float v = -FLT_MAX;
    int i = 0;
    for (; i + 4 <= n; i += 4) {
        int p0 = g_sorted[st + i + 0];
        int p1 = g_sorted[st + i + 1];
        int p2 = g_sorted[st + i + 2];
        int p3 = g_sorted[st + i + 3];
        float a = g_net[(size_t)p0 * H + ch];
        float b = g_net[(size_t)p1 * H + ch];
        float c = g_net[(size_t)p2 * H + ch];
        float d = g_net[(size_t)p3 * H + ch];
        v = fmaxf(v, fmaxf(fmaxf(a, b), fmaxf(c, d)));
    }
    for (; i < n; i++) {
        int p = g_sorted[st + i];
        v = fmaxf(v, g_net[(size_t)p * H + ch]);
    }
    g_plane[(size_t)bin * H + ch] = v;
}

// ---- plane mean: per-bin gather-sum, smem-transposed coalesced writes ----
__global__ void __launch_bounds__(128)
mean_kernel(float* __restrict__ out) {   // grid = 24*128 = 3072, block = 128
    __shared__ float tile[128][33];
    int pb = blockIdx.x >> 7;            // plane*BATCH + batch (0..23)
    int r0 = (blockIdx.x & 127) * 32;
    int ch = threadIdx.x;

    for (int bb = 0; bb < 32; bb++) {
        int bin = pb * R2 + r0 + bb;
        int n = g_cnt[bin];
        int st = g_start[bin];
        float s = 0.f;
        int i = 0;
        for (; i + 4 <= n; i += 4) {
            int p0 = g_sorted[st + i + 0];
            int p1 = g_sorted[st + i + 1];
            int p2 = g_sorted[st + i + 2];
            int p3 = g_sorted[st + i + 3];
            s += g_c[(size_t)p0 * H + ch] + g_c[(size_t)p1 * H + ch]
               + g_c[(size_t)p2 * H + ch] + g_c[(size_t)p3 * H + ch];
        }
        for (; i < n; i++) s += g_c[(size_t)g_sorted[st + i] * H + ch];
        tile[ch][bb] = s / (float)max(n, 1);
    }
    __syncthreads();

    int lane = ch & 31;
    int rowq = ch >> 5;
    for (int it = 0; it < 32; it++) {
        int row = it * 4 + rowq;
        out[((size_t)pb * H + row) * R2 + r0 + lane] = tile[row][lane];
    }
}

extern "C" void kernel_launch(void* const* d_in, const int* in_sizes, int n_in,
                              void* d_out, int out_size) {
    const float* pts  = (const float*)d_in[0];
    const int*   ixz  = (const int*)d_in[1];
    const int*   ixy  = (const int*)d_in[2];
    const int*   iyz  = (const int*)d_in[3];
    const float* fcpw = (const float*)d_in[4];
    const float* fcpb = (const float*)d_in[5];
    const float* fc0w = (const float*)d_in[6];
    const float* fc0b = (const float*)d_in[7];
    const float* fc1w = (const float*)d_in[8];
    const float* fc1b = (const float*)d_in[9];
    const float* scw  = (const float*)d_in[10];
    const float* fccw = (const float*)d_in[11];
    const float* fccb = (const float*)d_in[12];
    float* out = (float*)d_out;

    const int RSMEM = ((H2 + H) * PSTRIDE + 2 * KC * 128) * 4 + 3 * PTILE * 4; // 220672
    const int FSMEM = (H * PSTRIDE + 2 * KC * 128) * 4;                        //  83968
    cudaFuncSetAttribute(resnet_kernel, cudaFuncAttributeMaxDynamicSharedMemorySize, RSMEM);
    cudaFuncSetAttribute(proj_kernel,   cudaFuncAttributeMaxDynamicSharedMemorySize, FSMEM);

    // sorted-bin infra (indices fixed for this call)
    zero_meta_kernel<<<(CNTN + 255) / 256, 256>>>();
    count_kernel<<<(NPTS + 255) / 256, 256>>>(ixz, ixy, iyz);
    scan1_kernel<<<96, 1024>>>();
    scan2_kernel<<<1, 128>>>();
    scan3_kernel<<<(CNTN + 255) / 256, 256>>>();
    sortfill_kernel<<<(NPTS + 255) / 256, 256>>>(ixz, ixy, iyz);

    // block 0 (fc_pos fused)
    resnet_kernel<<<NTILES, 512, RSMEM>>>(0, pts, ixz, ixy, iyz, fcpw, fcpb,
                                          fc0w, fc0b, fc1w, fc1b, scw);
    // blocks 1..4 with pooling
    for (int it = 1; it < 5; it++) {
        pool_max_kernel<<<CNTN, 128>>>();
        resnet_kernel<<<NTILES, 512, RSMEM>>>(1, pts, ixz, ixy, iyz, fcpw, fcpb,
                                              fc0w + (size_t)it * H2 * H,
                                              fc0b + (size_t)it * H,
                                              fc1w + (size_t)it * H * H,
                                              fc1b + (size_t)it * H,
                                              scw  + (size_t)it * H2 * H);
    }
    // final projection + plane means
    proj_kernel<<<NTILES, 512, FSMEM>>>(fccw, fccb);
    mean_kernel<<<24 * 128, 128>>>(out);
}